// round 6
// baseline (speedup 1.0000x reference)
#include <cuda_runtime.h>
#include <cstddef>

typedef unsigned long long u64;

// Scratch (static __device__ — no allocations allowed).
__device__ float g_S[1966080];    // softmaxed weights, all 4 layers
__device__ float g_hA[2097152];   // 512*256*16 (layer1 out, reused by layer3 out)
__device__ float g_hB[1048576];   // 512*128*16 (layer2 out, reused by layer4 out)

// ---------------- packed f32x2 helpers (dual-fp32 pipe) --------------------
__device__ __forceinline__ void fma2(u64& d, u64 a, u64 b) {
    asm("fma.rn.f32x2 %0, %1, %2, %0;" : "+l"(d) : "l"(a), "l"(b));
}
__device__ __forceinline__ u64 pack2(float x) {
    u64 d; asm("mov.b64 %0, {%1, %1};" : "=l"(d) : "f"(x)); return d;
}
__device__ __forceinline__ void unpack2(u64 a, float& lo, float& hi) {
    asm("mov.b64 {%0, %1}, %2;" : "=f"(lo), "=f"(hi) : "l"(a));
}

// ---------------------------------------------------------------------------
// Kernel 1: weight softmax. One block per f-slice (480 blocks, 256 threads).
// ---------------------------------------------------------------------------
__global__ void __launch_bounds__(256) wsoftmax_kernel(
    const float* __restrict__ W1, const float* __restrict__ W2,
    const float* __restrict__ W3, const float* __restrict__ W4)
{
    __shared__ float Ssm[4096];
    __shared__ float red[256];
    __shared__ float mxk[16];

    const int bx = blockIdx.x;
    const int t  = threadIdx.x;
    const float* W; float* S; int f;
    if (bx < 256)      { W = W1; S = g_S;           f = bx;       }
    else if (bx < 384) { W = W2; S = g_S + 1048576; f = bx - 256; }
    else if (bx < 448) { W = W3; S = g_S + 1572864; f = bx - 384; }
    else               { W = W4; S = g_S + 1835008; f = bx - 448; }

    const float4* Wg = (const float4*)(W + (size_t)f * 4096);
    float4*       Sg = (float4*)(S + (size_t)f * 4096);

    #pragma unroll
    for (int q = 0; q < 4; q++) ((float4*)Ssm)[t + 256 * q] = Wg[t + 256 * q];
    __syncthreads();

    const int k = t & 15;
    const int g = t >> 4;

    float pm = -1e30f;
    #pragma unroll
    for (int mm = 0; mm < 16; mm++) pm = fmaxf(pm, Ssm[(g * 16 + mm) * 16 + k]);
    red[g * 16 + k] = pm;
    __syncthreads();
    #pragma unroll
    for (int st = 8; st > 0; st >>= 1) {
        if (g < st) red[g * 16 + k] = fmaxf(red[g * 16 + k], red[(g + st) * 16 + k]);
        __syncthreads();
    }
    if (g == 0) mxk[k] = red[k];
    __syncthreads();

    const float mx = mxk[k];
    float ps = 0.f;
    #pragma unroll
    for (int mm = 0; mm < 16; mm++) {
        int idx = (g * 16 + mm) * 16 + k;
        float e = __expf(Ssm[idx] - mx);
        Ssm[idx] = e;
        ps += e;
    }
    __syncthreads();
    red[g * 16 + k] = ps;
    __syncthreads();
    #pragma unroll
    for (int st = 8; st > 0; st >>= 1) {
        if (g < st) red[g * 16 + k] += red[(g + st) * 16 + k];
        __syncthreads();
    }
    const float inv = 1.f / red[k];
    #pragma unroll
    for (int mm = 0; mm < 16; mm++) Ssm[(g * 16 + mm) * 16 + k] *= inv;
    __syncthreads();

    #pragma unroll
    for (int q = 0; q < 4; q++) Sg[t + 256 * q] = ((float4*)Ssm)[t + 256 * q];
}

// ---------------------------------------------------------------------------
// Kernel 2: one SPN layer. Template on (KS = k-split, NT = n per thread).
//   128 threads = NSL n-slots x KS k-lanes; thread (nl,s) owns k-chunk
//   [KO*s, KO*s+KO), KO = 16/KS, and NT samples n0 (+ n1 = n0+NSL).
//   S reads: s-lanes hit distinct consecutive banks, nl-lanes broadcast ->
//   1 wavefront per load. b stored pair-interleaved (stride NT*16+2): one
//   LDS.64 fetches both samples' b_j. All grids sized to 1024 blocks
//   (27.7 warps/SM) to hide LDS latency.
// ---------------------------------------------------------------------------
template<int KS, int NT, int MINB>
__global__ void __launch_bounds__(128, MINB) layer_kernel(
    const float* __restrict__ hin, const float* __restrict__ Sall,
    float* __restrict__ hout, int F_in, int s_off)
{
    constexpr int KO   = 16 / KS;
    constexpr int NSL  = 128 / KS;
    constexpr int BSTR = NT * 16 + 2;    // 34 (NT=2) or 18 (NT=1)
    extern __shared__ float sm[];
    float* Ssm   = sm;                   // 4096 floats
    float* Brows = sm + 4096;            // NSL * BSTR floats

    const int tid = threadIdx.x;
    const int s   = tid % KS;
    const int nl  = tid / KS;
    const int f   = blockIdx.x;
    const int F_out = F_in >> 1;
    const int n0 = blockIdx.y * (NT * NSL) + nl;

    // Stage S_f (16KB), coalesced.
    {
        const float4* Sg = (const float4*)(Sall + (size_t)s_off + (size_t)f * 4096);
        #pragma unroll
        for (int q = 0; q < 8; q++) ((float4*)Ssm)[tid + 128 * q] = Sg[tid + 128 * q];
    }

    float a0[16], a1[16];
    float base0 = 0.f, base1 = 0.f;
    float* row = Brows + nl * BSTR;
    {
        float v[32];
        const float4* hp = (const float4*)(hin + ((size_t)n0 * F_in + 2 * f) * 16);
        #pragma unroll
        for (int q = 0; q < 8; q++) ((float4*)v)[q] = hp[q];
        float l = v[0], r = v[16];
        #pragma unroll
        for (int i = 1; i < 16; i++) { l = fmaxf(l, v[i]); r = fmaxf(r, v[16 + i]); }
        #pragma unroll
        for (int i = 0; i < 16; i++) a0[i] = __expf(v[i] - l);
        if (s == 0) {
            #pragma unroll
            for (int j = 0; j < 16; j++) row[NT * j] = __expf(v[16 + j] - r);
        }
        base0 = l + r;
    }
    if constexpr (NT == 2) {
        float v[32];
        const float4* hp = (const float4*)(hin + ((size_t)(n0 + NSL) * F_in + 2 * f) * 16);
        #pragma unroll
        for (int q = 0; q < 8; q++) ((float4*)v)[q] = hp[q];
        float l = v[0], r = v[16];
        #pragma unroll
        for (int i = 1; i < 16; i++) { l = fmaxf(l, v[i]); r = fmaxf(r, v[16 + i]); }
        #pragma unroll
        for (int i = 0; i < 16; i++) a1[i] = __expf(v[i] - l);
        if (s == 0) {
            #pragma unroll
            for (int j = 0; j < 16; j++) row[2 * j + 1] = __expf(v[16 + j] - r);
        }
        base1 = l + r;
    }
    __syncthreads();

    u64 acc0[KO / 2], acc1[KO / 2];
    #pragma unroll
    for (int u = 0; u < KO / 2; u++) { acc0[u] = 0ull; acc1[u] = 0ull; }

    #pragma unroll 2
    for (int j = 0; j < 16; j++) {
        float b0, b1;
        if constexpr (NT == 2) {
            u64 bb = ((const u64*)row)[j];
            unpack2(bb, b0, b1);
        } else {
            b0 = row[j];
        }
        const float* Sj = Ssm + j * 16 + KO * s;
        #pragma unroll
        for (int i = 0; i < 16; i++) {
            const u64* q = (const u64*)(Sj + i * 256);
            const u64 p0 = pack2(a0[i] * b0);
            #pragma unroll
            for (int u = 0; u < KO / 2; u++) fma2(acc0[u], p0, q[u]);
            if constexpr (NT == 2) {
                const u64 p1 = pack2(a1[i] * b1);
                #pragma unroll
                for (int u = 0; u < KO / 2; u++) fma2(acc1[u], p1, q[u]);
            }
        }
    }

    // Epilogue: log + store (KO floats per sample; k contiguous across s).
    {
        float o[KO];
        #pragma unroll
        for (int u = 0; u < KO / 2; u++) {
            float lo, hi; unpack2(acc0[u], lo, hi);
            o[2 * u] = __logf(lo) + base0;  o[2 * u + 1] = __logf(hi) + base0;
        }
        float* op = hout + ((size_t)n0 * F_out + f) * 16 + KO * s;
        if constexpr (KO >= 4) {
            #pragma unroll
            for (int q = 0; q < KO / 4; q++) ((float4*)op)[q] = ((float4*)o)[q];
        } else {
            ((float2*)op)[0] = make_float2(o[0], o[1]);
        }
    }
    if constexpr (NT == 2) {
        float o[KO];
        #pragma unroll
        for (int u = 0; u < KO / 2; u++) {
            float lo, hi; unpack2(acc1[u], lo, hi);
            o[2 * u] = __logf(lo) + base1;  o[2 * u + 1] = __logf(hi) + base1;
        }
        float* op = hout + ((size_t)(n0 + NSL) * F_out + f) * 16 + KO * s;
        if constexpr (KO >= 4) {
            #pragma unroll
            for (int q = 0; q < KO / 4; q++) ((float4*)op)[q] = ((float4*)o)[q];
        } else {
            ((float2*)op)[0] = make_float2(o[0], o[1]);
        }
    }
}

// ---------------------------------------------------------------------------
// Kernel 3: root. Block per n (512 blocks, 32 threads), warp-shfl reduce.
// ---------------------------------------------------------------------------
__global__ void __launch_bounds__(32) root_kernel(
    const float* __restrict__ h4, const float* __restrict__ Wroot,
    float* __restrict__ out)
{
    const int n = blockIdx.x;
    const int t = threadIdx.x;
    const float4* hp = (const float4*)(h4 + (size_t)n * 512);

    float4 a = make_float4(0.f, 0.f, 0.f, 0.f);
    #pragma unroll
    for (int r = 0; r < 4; r++) {
        float4 q = hp[t + 32 * r];
        a.x += q.x; a.y += q.y; a.z += q.z; a.w += q.w;
    }
    #pragma unroll
    for (int st = 4; st <= 16; st <<= 1) {
        a.x += __shfl_xor_sync(0xffffffffu, a.x, st);
        a.y += __shfl_xor_sync(0xffffffffu, a.y, st);
        a.z += __shfl_xor_sync(0xffffffffu, a.z, st);
        a.w += __shfl_xor_sync(0xffffffffu, a.w, st);
    }
    __shared__ float sred[16];
    if (t < 4) { sred[4*t] = a.x; sred[4*t+1] = a.y; sred[4*t+2] = a.z; sred[4*t+3] = a.w; }
    __syncwarp();

    if (t == 0) {
        float w[16];
        #pragma unroll
        for (int k = 0; k < 16; k++) w[k] = Wroot[k];
        float wm = w[0];
        #pragma unroll
        for (int k = 1; k < 16; k++) wm = fmaxf(wm, w[k]);
        float Z = 0.f;
        #pragma unroll
        for (int k = 0; k < 16; k++) Z += __expf(w[k] - wm);
        const float lz = __logf(Z) + wm;

        float tv[16];
        float tm = -1e30f;
        #pragma unroll
        for (int k = 0; k < 16; k++) {
            tv[k] = sred[k] + w[k] - lz;
            tm = fmaxf(tm, tv[k]);
        }
        float ss = 0.f;
        #pragma unroll
        for (int k = 0; k < 16; k++) ss += __expf(tv[k] - tm);
        out[n] = __logf(ss) + tm;
    }
}

// ---------------------------------------------------------------------------
extern "C" void kernel_launch(void* const* d_in, const int* in_sizes, int n_in,
                              void* d_out, int out_size)
{
    const float* x  = (const float*)d_in[0];
    const float* W1 = (const float*)d_in[1];
    const float* W2 = (const float*)d_in[2];
    const float* W3 = (const float*)d_in[3];
    const float* W4 = (const float*)d_in[4];
    const float* Wr = (const float*)d_in[5];
    float* out = (float*)d_out;

    float *S, *hA, *hB;
    cudaGetSymbolAddress((void**)&S,  g_S);
    cudaGetSymbolAddress((void**)&hA, g_hA);
    cudaGetSymbolAddress((void**)&hB, g_hB);

    wsoftmax_kernel<<<480, 256>>>(W1, W2, W3, W4);

    // smem = 16KB (S) + NSL*BSTR*4 (b rows); all grids = 1024 blocks.
    const size_t smA = 16384 + 64 * 34 * 4;   // KS=2, NT=2: 25088
    const size_t smB = 16384 + 32 * 34 * 4;   // KS=4, NT=2: 20736
    const size_t smC = 16384 + 16 * 34 * 4;   // KS=8, NT=2: 18560
    const size_t smD = 16384 + 16 * 18 * 4;   // KS=8, NT=1: 17536

    layer_kernel<2, 2, 6><<<dim3(256, 4),  128, smA>>>(x,  S, hA, 512, 0);
    layer_kernel<4, 2, 6><<<dim3(128, 8),  128, smB>>>(hA, S, hB, 256, 1048576);
    layer_kernel<8, 2, 6><<<dim3(64, 16),  128, smC>>>(hB, S, hA, 128, 1572864);
    layer_kernel<8, 1, 6><<<dim3(32, 32),  128, smD>>>(hA, S, hB, 64,  1835008);

    root_kernel<<<512, 32>>>(hB, Wr, out);
}